// round 6
// baseline (speedup 1.0000x reference)
#include <cuda_runtime.h>
#include <cstdint>

// MaxUnpooling2D: out[B,H2,W2,C] zeros except out[mask[i]] = updates[i].
// Collision-free mask => no atomics. Each thread owns one 2x2 window for an
// 8-channel group; writes all 4 cells (zeros + value) with 256-bit stores
// (st.global.v8.f32, sm_100a). Warp store = 1024B contiguous (full cell row).
//
// Shapes (fixed): B=16, H=W=64, C=256, up=(2,2) -> H2=W2=128.

#define C_    256
#define W2C   32768            // W2 * C
#define TOTAL8 (1 << 21)       // B*H*W*(C/8) = 16*64*64*32

#define STG256(ptr, v) \
    asm volatile("st.global.v8.f32 [%0], {%1,%2,%3,%4,%5,%6,%7,%8};" \
        :: "l"(ptr), "f"((v)[0]), "f"((v)[1]), "f"((v)[2]), "f"((v)[3]), \
                     "f"((v)[4]), "f"((v)[5]), "f"((v)[6]), "f"((v)[7]) : "memory")

__global__ __launch_bounds__(256) void maxunpool_kernel(
    const float4* __restrict__ upd4,
    const int4*   __restrict__ msk4,
    float*        __restrict__ out)
{
    const unsigned t = blockIdx.x * blockDim.x + threadIdx.x;   // [0, 2^21)

    // Two adjacent 4-channel sub-groups of the same window cell.
    const float4 ua = upd4[2u * t];
    const float4 ub = upd4[2u * t + 1u];
    const int4   ma = msk4[2u * t];
    const int4   mb = msk4[2u * t + 1u];

    // t = ((b*64 + h)*64 + w)*32 + c8
    // base = (b*128+2h)*128*256 + (2w)*256 + 8*c8
    const unsigned base = ((t >> 17) << 22)
                        | (((t >> 11) & 63u) << 16)
                        | (((t >> 5)  & 63u) << 9)
                        | ((t & 31u) << 3);

    // mask: c = bits[0:8), x = bits[8:15), y = bits[15:22)
    // dx = bit 8, dy = bit 15; slot k = 2*dy + dx
    int k[8];
    k[0] = ((ma.x >> 14) & 2) | ((ma.x >> 8) & 1);
    k[1] = ((ma.y >> 14) & 2) | ((ma.y >> 8) & 1);
    k[2] = ((ma.z >> 14) & 2) | ((ma.z >> 8) & 1);
    k[3] = ((ma.w >> 14) & 2) | ((ma.w >> 8) & 1);
    k[4] = ((mb.x >> 14) & 2) | ((mb.x >> 8) & 1);
    k[5] = ((mb.y >> 14) & 2) | ((mb.y >> 8) & 1);
    k[6] = ((mb.z >> 14) & 2) | ((mb.z >> 8) & 1);
    k[7] = ((mb.w >> 14) & 2) | ((mb.w >> 8) & 1);

    float uu[8] = { ua.x, ua.y, ua.z, ua.w, ub.x, ub.y, ub.z, ub.w };

    float v0[8], v1[8], v2[8], v3[8];   // (dy,dx) = (0,0),(0,1),(1,0),(1,1)
#pragma unroll
    for (int i = 0; i < 8; ++i) {
        v0[i] = (k[i] == 0) ? uu[i] : 0.0f;
        v1[i] = (k[i] == 1) ? uu[i] : 0.0f;
        v2[i] = (k[i] == 2) ? uu[i] : 0.0f;
        v3[i] = (k[i] == 3) ? uu[i] : 0.0f;
    }

    STG256(out + base,            v0);  // (2h,   2w)
    STG256(out + base + C_,       v1);  // (2h,   2w+1)
    STG256(out + base + W2C,      v2);  // (2h+1, 2w)
    STG256(out + base + W2C + C_, v3);  // (2h+1, 2w+1)
}

extern "C" void kernel_launch(void* const* d_in, const int* in_sizes, int n_in,
                              void* d_out, int out_size)
{
    const float4* upd4 = reinterpret_cast<const float4*>(d_in[0]);
    const int4*   msk4 = reinterpret_cast<const int4*>(d_in[1]);
    float*        out  = reinterpret_cast<float*>(d_out);

    const int threads = 256;
    const int blocks  = TOTAL8 / threads;   // 8192

    maxunpool_kernel<<<blocks, threads>>>(upd4, msk4, out);
}

// round 7
// speedup vs baseline: 1.0010x; 1.0010x over previous
#include <cuda_runtime.h>
#include <cstdint>

// MaxUnpooling2D: out[B,H2,W2,C] zeros except out[mask[i]] = updates[i].
// Collision-free mask => no atomics. Each thread owns one 2x2 window for a
// 4-channel group and writes all 4 cells (3 zeros + value). No zero-fill pass.
//
// R7: identical code to R5 (champion, 59.36us); single variable changed:
// block 256 -> 1024 (grid 16384 -> 4096). Same linear index map, but each
// resident block now covers 2 x 32KB contiguous output runs (vs 2 x 8KB),
// lengthening same-direction DRAM bursts per SM.
//
// Shapes (fixed): B=16, H=W=64, C=256, up=(2,2) -> H2=W2=128.

#define C_   256
#define W2C  32768           // W2 * C
#define TOTAL4 (1 << 22)     // B*H*W*(C/4) = 16*64*64*64

__global__ __launch_bounds__(1024) void maxunpool_kernel(
    const float4* __restrict__ upd4,
    const int4*   __restrict__ msk4,
    float*        __restrict__ out)
{
    const unsigned t = blockIdx.x * blockDim.x + threadIdx.x;

    const float4 u = upd4[t];
    const int4   m = msk4[t];

    // t = ((b*64 + h)*64 + w)*64 + c4
    // base = (b*128 + 2h)*128*256 + (2w)*256 + 4*c4  (all powers of 2)
    const unsigned base = ((t >> 18) << 22)
                        | (((t >> 12) & 63u) << 16)
                        | (((t >> 6)  & 63u) << 9)
                        | ((t & 63u) << 2);

    // mask layout: c = bits[0:8), x = bits[8:15), y = bits[15:22)
    // dx = bit 8, dy = bit 15; slot k = 2*dy + dx
    const int k0 = ((m.x >> 14) & 2) | ((m.x >> 8) & 1);
    const int k1 = ((m.y >> 14) & 2) | ((m.y >> 8) & 1);
    const int k2 = ((m.z >> 14) & 2) | ((m.z >> 8) & 1);
    const int k3 = ((m.w >> 14) & 2) | ((m.w >> 8) & 1);

    float4 v0, v1, v2, v3;  // (dy,dx) = (0,0),(0,1),(1,0),(1,1)
    v0.x = (k0 == 0) ? u.x : 0.0f;  v0.y = (k1 == 0) ? u.y : 0.0f;
    v0.z = (k2 == 0) ? u.z : 0.0f;  v0.w = (k3 == 0) ? u.w : 0.0f;
    v1.x = (k0 == 1) ? u.x : 0.0f;  v1.y = (k1 == 1) ? u.y : 0.0f;
    v1.z = (k2 == 1) ? u.z : 0.0f;  v1.w = (k3 == 1) ? u.w : 0.0f;
    v2.x = (k0 == 2) ? u.x : 0.0f;  v2.y = (k1 == 2) ? u.y : 0.0f;
    v2.z = (k2 == 2) ? u.z : 0.0f;  v2.w = (k3 == 2) ? u.w : 0.0f;
    v3.x = (k0 == 3) ? u.x : 0.0f;  v3.y = (k1 == 3) ? u.y : 0.0f;
    v3.z = (k2 == 3) ? u.z : 0.0f;  v3.w = (k3 == 3) ? u.w : 0.0f;

    __stcs(reinterpret_cast<float4*>(out + base),             v0); // (2h,  2w)
    __stcs(reinterpret_cast<float4*>(out + base + C_),        v1); // (2h,  2w+1)
    __stcs(reinterpret_cast<float4*>(out + base + W2C),       v2); // (2h+1,2w)
    __stcs(reinterpret_cast<float4*>(out + base + W2C + C_),  v3); // (2h+1,2w+1)
}

extern "C" void kernel_launch(void* const* d_in, const int* in_sizes, int n_in,
                              void* d_out, int out_size)
{
    const float4* upd4 = reinterpret_cast<const float4*>(d_in[0]);
    const int4*   msk4 = reinterpret_cast<const int4*>(d_in[1]);
    float*        out  = reinterpret_cast<float*>(d_out);

    const int threads = 1024;
    const int blocks  = TOTAL4 / threads;   // 4096

    maxunpool_kernel<<<blocks, threads>>>(upd4, msk4, out);
}